// round 3
// baseline (speedup 1.0000x reference)
#include <cuda_runtime.h>
#include <cuda_bf16.h>

// Problem constants
#define NB 32            // N
#define MODES 4
#define EYS 192          // EY_SIZE
#define EY_PLANE (EYS*EYS)          // 36864 floats
#define EY_PLANE4 (EY_PLANE/4)      // 9216 float4
#define EYROW4 (EYS/4)              // 48 float4 per Ey row
#define TOTAL 1184       // (N + 2*KNN + 1) * OUT_RES
#define NK (NB*NB)       // 1024

// Scratch: precomputed weights w[k][m] = U * neff*N0/(neff+N0), laid out [k*4+m]
__device__ float g_w[NK * MODES];

__global__ void compute_weights_kernel(const float* __restrict__ U,
                                       const float* __restrict__ neff) {
    int idx = blockIdx.x * blockDim.x + threadIdx.x;
    if (idx < NK * MODES) {
        float nf = neff[idx];
        float eta = nf * 1.5f / (nf + 1.5f);
        g_w[idx] = eta * U[idx];
    }
}

// Each thread: 2 consecutive output rows x 4 consecutive columns.
// Per (i,j) iteration: 8 independent LDG.128s (4 modes x 2 rows) -> high MLP.
// All Ey bytes read exactly once chip-wide, fully coalesced, streamed (__ldcs).
// blockDim = (32, 8); each CTA covers 16 rows x 128 cols.
// grid = (ceil(1184/128)=10, 1184/16=74).
__global__ __launch_bounds__(256) void gather_en_kernel(
    const float* __restrict__ Ey,
    float* __restrict__ out)
{
    const int lane = threadIdx.x;
    const int r    = blockIdx.y * 16 + threadIdx.y * 2;  // 0..1182, uniform per warp
    const int c    = blockIdx.x * 128 + lane * 4;        // 16B-aligned column
    const bool active = (c < TOTAL);

    // Union of i-ranges for rows r and r+1 (uniform per warp)
    int i_lo = (r - 160) >> 5;     if (i_lo < 0) i_lo = 0;        // i_lo(r) <= i_lo(r+1)
    int i_hi = (r + 1) >> 5;       if (i_hi > NB - 1) i_hi = NB - 1; // i_hi(r+1) >= i_hi(r)

    // j-range per lane
    int j_lo = (c - 160) >> 5; if (j_lo < 0) j_lo = 0;
    int j_hi = c >> 5;         if (j_hi > NB - 1) j_hi = NB - 1;
    if (!active) { j_lo = 1; j_hi = 0; }

    const float4* __restrict__ w4  = reinterpret_cast<const float4*>(g_w);
    const float4* __restrict__ Ey4 = reinterpret_cast<const float4*>(Ey);

    float4 accA = make_float4(0.f, 0.f, 0.f, 0.f);   // row r
    float4 accB = make_float4(0.f, 0.f, 0.f, 0.f);   // row r+1

    const float4 zero = make_float4(0.f, 0.f, 0.f, 0.f);

    for (int i = i_lo; i <= i_hi; ++i) {
        const int x = r - (i << 5);                          // row-r offset in block
        const bool vA = ((unsigned)x < (unsigned)EYS);       // row r valid
        const bool vB = ((unsigned)(x + 1) < (unsigned)EYS); // row r+1 valid
        const long base_i = (long)(i << 5) * (MODES * EY_PLANE4) + (long)x * EYROW4;

        for (int j = j_lo; j <= j_hi; ++j) {
            const int k  = (i << 5) + j;
            const int y4 = (c - (j << 5)) >> 2;              // 0..47
            const float4* p = Ey4 + base_i + (long)j * (MODES * EY_PLANE4) + y4;
            const float4 wv = __ldg(&w4[k]);                 // uniform per warp, L1-hot

            // 8 independent streaming loads before any dependent math
            const float4 a0 = vA ? __ldcs(p)                         : zero;
            const float4 a1 = vA ? __ldcs(p + EY_PLANE4)             : zero;
            const float4 a2 = vA ? __ldcs(p + 2 * EY_PLANE4)         : zero;
            const float4 a3 = vA ? __ldcs(p + 3 * EY_PLANE4)         : zero;
            const float4 b0 = vB ? __ldcs(p + EYROW4)                : zero;
            const float4 b1 = vB ? __ldcs(p + EYROW4 + EY_PLANE4)    : zero;
            const float4 b2 = vB ? __ldcs(p + EYROW4 + 2*EY_PLANE4)  : zero;
            const float4 b3 = vB ? __ldcs(p + EYROW4 + 3*EY_PLANE4)  : zero;

            accA.x += wv.x * a0.x + wv.y * a1.x + wv.z * a2.x + wv.w * a3.x;
            accA.y += wv.x * a0.y + wv.y * a1.y + wv.z * a2.y + wv.w * a3.y;
            accA.z += wv.x * a0.z + wv.y * a1.z + wv.z * a2.z + wv.w * a3.z;
            accA.w += wv.x * a0.w + wv.y * a1.w + wv.z * a2.w + wv.w * a3.w;

            accB.x += wv.x * b0.x + wv.y * b1.x + wv.z * b2.x + wv.w * b3.x;
            accB.y += wv.x * b0.y + wv.y * b1.y + wv.z * b2.y + wv.w * b3.y;
            accB.z += wv.x * b0.z + wv.y * b1.z + wv.z * b2.z + wv.w * b3.z;
            accB.w += wv.x * b0.w + wv.y * b1.w + wv.z * b2.w + wv.w * b3.w;
        }
    }

    if (active) {
        __stcs(reinterpret_cast<float4*>(out + (long)r * TOTAL + c), accA);
        __stcs(reinterpret_cast<float4*>(out + (long)(r + 1) * TOTAL + c), accB);
    }
}

extern "C" void kernel_launch(void* const* d_in, const int* in_sizes, int n_in,
                              void* d_out, int out_size) {
    // Inputs (metadata order): hs (unused), U, neff, Ey
    const float* U    = (const float*)d_in[1];
    const float* neff = (const float*)d_in[2];
    const float* Ey   = (const float*)d_in[3];
    float* out = (float*)d_out;

    compute_weights_kernel<<<(NK * MODES + 255) / 256, 256>>>(U, neff);

    dim3 block(32, 8);
    dim3 grid((TOTAL + 127) / 128, TOTAL / 16);   // (10, 74)
    gather_en_kernel<<<grid, block>>>(Ey, out);
}